// round 12
// baseline (speedup 1.0000x reference)
#include <cuda_runtime.h>
#include <cuda_bf16.h>
#include <math.h>
#include <stdint.h>

#define D_MODEL 1024
#define N_HEADS 16
#define HEAD_DIM 64
#define SEQ 2048
#define MAXB 2

typedef unsigned short ushort_t;

// ---------------- scratch (no allocations allowed) ----------------
__device__ __align__(1024) float g_q[MAXB * N_HEADS * SEQ * HEAD_DIM];
__device__ __align__(1024) float g_k[MAXB * N_HEADS * SEQ * HEAD_DIM];
__device__ __align__(1024) ushort_t g_qh[MAXB * N_HEADS * SEQ * HEAD_DIM];
__device__ __align__(1024) ushort_t g_ql[MAXB * N_HEADS * SEQ * HEAD_DIM];
__device__ __align__(1024) ushort_t g_kh[MAXB * N_HEADS * SEQ * HEAD_DIM];
__device__ __align__(1024) ushort_t g_kl[MAXB * N_HEADS * SEQ * HEAD_DIM];
__device__ __align__(1024) ushort_t g_vh[MAXB * N_HEADS * SEQ * HEAD_DIM];
__device__ __align__(1024) ushort_t g_vl[MAXB * N_HEADS * SEQ * HEAD_DIM];
__device__ __align__(1024) ushort_t g_xh[MAXB * SEQ * D_MODEL];   // bf16 hi of x / attn-out
__device__ __align__(1024) ushort_t g_xl[MAXB * SEQ * D_MODEL];   // bf16 lo
__device__ __align__(1024) ushort_t g_wh[4 * D_MODEL * D_MODEL];  // bf16 hi of weights
__device__ __align__(1024) ushort_t g_wl[4 * D_MODEL * D_MODEL];

// ---------------- helpers ----------------
__device__ __forceinline__ uint32_t stou(const void* p) {
    uint32_t a;
    asm("{ .reg .u64 t; cvta.to.shared.u64 t, %1; cvt.u32.u64 %0, t; }"
        : "=r"(a) : "l"(p));
    return a;
}
__device__ __forceinline__ uint32_t bfpack(float lo, float hi) {
    uint32_t r;
    asm("cvt.rn.bf16x2.f32 %0, %1, %2;" : "=r"(r) : "f"(hi), "f"(lo));
    return r;
}
__device__ __forceinline__ float bfr(float x) {   // round to bf16, back to float
    return __bfloat162float(__float2bfloat16_rn(x));
}
__device__ __forceinline__ ushort_t bfu(float x) {
    __nv_bfloat16_raw r = __float2bfloat16_rn(x);
    return r.x;
}
__device__ __forceinline__ void cpasync16(uint32_t dst, const void* src) {
    asm volatile("cp.async.cg.shared.global [%0], [%1], 16;"
                 :: "r"(dst), "l"(src) : "memory");
}
#define CP_COMMIT() asm volatile("cp.async.commit_group;" ::: "memory")
#define CP_WAIT1()  asm volatile("cp.async.wait_group 1;" ::: "memory")
#define CP_WAIT0()  asm volatile("cp.async.wait_group 0;" ::: "memory")

__device__ __forceinline__ void ldx4(uint32_t r[4], uint32_t addr) {
    asm volatile("ldmatrix.sync.aligned.m8n8.x4.shared.b16 {%0,%1,%2,%3}, [%4];"
                 : "=r"(r[0]), "=r"(r[1]), "=r"(r[2]), "=r"(r[3]) : "r"(addr));
}
__device__ __forceinline__ void ldx4t(uint32_t r[4], uint32_t addr) {
    asm volatile("ldmatrix.sync.aligned.m8n8.x4.trans.shared.b16 {%0,%1,%2,%3}, [%4];"
                 : "=r"(r[0]), "=r"(r[1]), "=r"(r[2]), "=r"(r[3]) : "r"(addr));
}
__device__ __forceinline__ void mma_bf(float c[4], const uint32_t a[4],
                                       uint32_t b0, uint32_t b1) {
    asm volatile(
        "mma.sync.aligned.m16n8k16.row.col.f32.bf16.bf16.f32 "
        "{%0,%1,%2,%3}, {%4,%5,%6,%7}, {%8,%9}, {%0,%1,%2,%3};"
        : "+f"(c[0]), "+f"(c[1]), "+f"(c[2]), "+f"(c[3])
        : "r"(a[0]), "r"(a[1]), "r"(a[2]), "r"(a[3]), "r"(b0), "r"(b1));
}

// ---------------- split kernels (fp32 -> bf16 hi + bf16 lo) ----------------
__global__ void split_kernel(const float4* __restrict__ src, uint2* __restrict__ hi,
                             uint2* __restrict__ lo, int n4) {
    int i = blockIdx.x * 256 + threadIdx.x;
    if (i >= n4) return;
    float4 v = src[i];
    float hx = bfr(v.x), hy = bfr(v.y), hz = bfr(v.z), hw = bfr(v.w);
    uint2 h, l;
    h.x = bfpack(hx, hy); h.y = bfpack(hz, hw);
    l.x = bfpack(v.x - hx, v.y - hy); l.y = bfpack(v.z - hz, v.w - hw);
    hi[i] = h; lo[i] = l;
}

__global__ void splitw_kernel(const float* __restrict__ w0, const float* __restrict__ w1,
                              const float* __restrict__ w2, const float* __restrict__ w3,
                              ushort_t* __restrict__ hi, ushort_t* __restrict__ lo) {
    int y = blockIdx.y;
    const float* w = (y == 0) ? w0 : (y == 1) ? w1 : (y == 2) ? w2 : w3;
    const int n4 = (D_MODEL * D_MODEL) / 4;
    const float4* s4 = (const float4*)w;
    uint2* h4 = (uint2*)(hi + (size_t)y * D_MODEL * D_MODEL);
    uint2* l4 = (uint2*)(lo + (size_t)y * D_MODEL * D_MODEL);
    for (int i = blockIdx.x * 256 + threadIdx.x; i < n4; i += gridDim.x * 256) {
        float4 v = s4[i];
        float hx = bfr(v.x), hy = bfr(v.y), hz = bfr(v.z), hw = bfr(v.w);
        uint2 h, l;
        h.x = bfpack(hx, hy); h.y = bfpack(hz, hw);
        l.x = bfpack(v.x - hx, v.y - hy); l.y = bfpack(v.z - hz, v.w - hw);
        h4[i] = h; l4[i] = l;
    }
}

// ---------------------------------------------------------------------------
// bf16 split GEMM: D = Ah*Bh^T + Al*Bh^T + Ah*Bl^T via m16n8k16 + ldmatrix.
// Tile 128x128, BK=32, 8 warps (2x4), warp tile 64x32, cp.async 2-stage.
// QKV=1: z=0 -> q fp32 [B,H,S,HD]; z=1 -> k fp32; z=2 -> V split bf16 VH/VL.
// QKV=0: fp32 row-major out.
// ---------------------------------------------------------------------------
#define GP 80
#define OPB (128 * GP)
#define STAGEB (4 * OPB)
#define NCH (D_MODEL / 32)

template <int QKV>
__global__ void __launch_bounds__(256, 1) tc_gemm(
    const ushort_t* __restrict__ Ah, const ushort_t* __restrict__ Al,
    const ushort_t* __restrict__ Wh, const ushort_t* __restrict__ Wl,
    float* __restrict__ C0, float* __restrict__ C1,
    ushort_t* __restrict__ VH, ushort_t* __restrict__ VL, int S) {
    extern __shared__ char smc[];
    uint32_t sb = stou(smc);

    int tid = threadIdx.x;
    int lane = tid & 31;
    int wid = tid >> 5;
    int warp_m = wid >> 2;
    int warp_n = wid & 3;

    int mBase = blockIdx.x * 128;
    int nBase = blockIdx.y * 128;

    const ushort_t* Bh = Wh;
    const ushort_t* Bl = Wl;
    if (QKV) {
        size_t woff = (size_t)blockIdx.z * D_MODEL * D_MODEL;
        Bh = Wh + woff; Bl = Wl + woff;
    }

    int r = tid >> 2, sg = tid & 3;
    const ushort_t* pAh = Ah + (size_t)(mBase + r) * D_MODEL + sg * 8;
    const ushort_t* pAl = Al + (size_t)(mBase + r) * D_MODEL + sg * 8;
    const ushort_t* pBh = Bh + (size_t)(nBase + r) * D_MODEL + sg * 8;
    const ushort_t* pBl = Bl + (size_t)(nBase + r) * D_MODEL + sg * 8;
    uint32_t dst0 = (uint32_t)(r * GP + sg * 16);
    const uint32_t rStep = 64 * GP;
    const size_t gStep = (size_t)64 * D_MODEL;

#define STAGE(buf, k0)                                                        \
    do {                                                                      \
        uint32_t s0 = sb + (uint32_t)(buf) * STAGEB + dst0;                   \
        cpasync16(s0,                  pAh + (k0));                           \
        cpasync16(s0 + rStep,          pAh + (k0) + gStep);                   \
        cpasync16(s0 + OPB,            pAl + (k0));                           \
        cpasync16(s0 + OPB + rStep,    pAl + (k0) + gStep);                   \
        cpasync16(s0 + 2 * OPB,        pBh + (k0));                          \
        cpasync16(s0 + 2 * OPB + rStep,pBh + (k0) + gStep);                   \
        cpasync16(s0 + 3 * OPB,        pBl + (k0));                          \
        cpasync16(s0 + 3 * OPB + rStep,pBl + (k0) + gStep);                   \
    } while (0)

    float c[4][4][4];
#pragma unroll
    for (int mi = 0; mi < 4; ++mi)
#pragma unroll
        for (int ni = 0; ni < 4; ++ni)
#pragma unroll
            for (int q = 0; q < 4; ++q) c[mi][ni][q] = 0.0f;

    uint32_t aOff = (uint32_t)((warp_m * 64 + (lane & 15)) * GP + (lane >> 4) * 16);
    uint32_t bOff = (uint32_t)((warp_n * 32 + (lane & 15)) * GP + (lane >> 4) * 16);

    STAGE(0, 0);
    CP_COMMIT();

    for (int ch = 0; ch < NCH; ++ch) {
        if (ch + 1 < NCH) {
            STAGE((ch + 1) & 1, (ch + 1) * 32);
            CP_COMMIT();
            CP_WAIT1();
        } else {
            CP_WAIT0();
        }
        __syncthreads();

        uint32_t stg = sb + (uint32_t)(ch & 1) * STAGEB;
#pragma unroll
        for (int ks = 0; ks < 2; ++ks) {
            uint32_t ah[4][4], al[4][4], bh4[2][4], bl4[2][4];
#pragma unroll
            for (int mi = 0; mi < 4; ++mi) {
                uint32_t a = stg + aOff + (uint32_t)(mi * 16 * GP + ks * 32);
                ldx4(ah[mi], a);
                ldx4(al[mi], a + OPB);
            }
#pragma unroll
            for (int np = 0; np < 2; ++np) {
                uint32_t a = stg + 2 * OPB + bOff + (uint32_t)(np * 16 * GP + ks * 32);
                ldx4(bh4[np], a);
                ldx4(bl4[np], a + OPB);
            }
#pragma unroll
            for (int mi = 0; mi < 4; ++mi)
#pragma unroll
                for (int np = 0; np < 2; ++np) {
                    mma_bf(c[mi][2 * np], ah[mi], bh4[np][0], bh4[np][2]);
                    mma_bf(c[mi][2 * np], al[mi], bh4[np][0], bh4[np][2]);
                    mma_bf(c[mi][2 * np], ah[mi], bl4[np][0], bl4[np][2]);
                    mma_bf(c[mi][2 * np + 1], ah[mi], bh4[np][1], bh4[np][3]);
                    mma_bf(c[mi][2 * np + 1], al[mi], bh4[np][1], bh4[np][3]);
                    mma_bf(c[mi][2 * np + 1], ah[mi], bl4[np][1], bl4[np][3]);
                }
        }
        __syncthreads();
    }
#undef STAGE

    int g = lane >> 2, t = lane & 3;
#pragma unroll
    for (int mi = 0; mi < 4; ++mi) {
#pragma unroll
        for (int ni = 0; ni < 4; ++ni) {
            int r0 = mBase + warp_m * 64 + mi * 16 + g;
            int cc = nBase + warp_n * 32 + ni * 8 + 2 * t;
            float2 v0 = make_float2(c[mi][ni][0], c[mi][ni][1]);
            float2 v1 = make_float2(c[mi][ni][2], c[mi][ni][3]);
            if (!QKV) {
                float* C = C0;
                *(float2*)(C + (size_t)r0 * D_MODEL + cc) = v0;
                *(float2*)(C + (size_t)(r0 + 8) * D_MODEL + cc) = v1;
            } else {
                int h = cc >> 6, hd = cc & 63;
                int b0 = r0 / S, s0 = r0 - b0 * S;
                int r1 = r0 + 8;
                int b1 = r1 / S, s1 = r1 - b1 * S;
                size_t o0 = (((size_t)b0 * N_HEADS + h) * S + s0) * HEAD_DIM + hd;
                size_t o1 = (((size_t)b1 * N_HEADS + h) * S + s1) * HEAD_DIM + hd;
                if (blockIdx.z == 2) {
                    // V: write split bf16 directly
                    float h0 = bfr(v0.x), h1 = bfr(v0.y);
                    *(uint32_t*)(VH + o0) = bfpack(h0, h1);
                    *(uint32_t*)(VL + o0) = bfpack(v0.x - h0, v0.y - h1);
                    float h2 = bfr(v1.x), h3 = bfr(v1.y);
                    *(uint32_t*)(VH + o1) = bfpack(h2, h3);
                    *(uint32_t*)(VL + o1) = bfpack(v1.x - h2, v1.y - h3);
                } else {
                    float* C = (blockIdx.z == 0) ? C0 : C1;
                    *(float2*)(C + o0) = v0;
                    *(float2*)(C + o1) = v1;
                }
            }
        }
    }
}

// ---------------------------------------------------------------------------
// Fused RoPE + bf16 split for Q (pre-scaled by 1/8) and K. [BH, S, HD].
// ---------------------------------------------------------------------------
__global__ void rope_split(const float* __restrict__ q, const float* __restrict__ k,
                           ushort_t* __restrict__ qh, ushort_t* __restrict__ ql,
                           ushort_t* __restrict__ kh, ushort_t* __restrict__ kl,
                           int BH, int S) {
    int idx = blockIdx.x * blockDim.x + threadIdx.x;
    int total = BH * S * 32;
    if (idx >= total) return;
    int j = idx & 31;
    int s = (idx >> 5) % S;
    int bh = idx / (32 * S);

    float inv = powf(10000.0f, -(float)j / 32.0f);
    float ang = (float)s * inv;
    float sn, cs;
    sincosf(ang, &sn, &cs);

    size_t base = ((size_t)bh * S + s) * HEAD_DIM;
    float q1 = q[base + j], q2 = q[base + j + 32];
    float qa = (q1 * cs - q2 * sn) * 0.125f;
    float qb = (q2 * cs + q1 * sn) * 0.125f;
    float qah = bfr(qa), qbh = bfr(qb);
    qh[base + j] = bfu(qa);          ql[base + j] = bfu(qa - qah);
    qh[base + j + 32] = bfu(qb);     ql[base + j + 32] = bfu(qb - qbh);

    float k1 = k[base + j], k2 = k[base + j + 32];
    float ka = k1 * cs - k2 * sn;
    float kb = k2 * cs + k1 * sn;
    float kah = bfr(ka), kbh = bfr(kb);
    kh[base + j] = bfu(ka);          kl[base + j] = bfu(ka - kah);
    kh[base + j + 32] = bfu(kb);     kl[base + j + 32] = bfu(kb - kbh);
}

// ---------------------------------------------------------------------------
// Flash attention, split-bf16, pre-split inputs. 64 q/CTA, 64-key tiles,
// 4 warps; warp owns rows [16w,16w+16) end-to-end (P stays in registers).
// 2-stage cp.async pipeline of bf16 K/V tiles; no per-tile split pass.
// ---------------------------------------------------------------------------
#define FPB 144               // bytes per 64-bf16 row (128 + 16 pad)
#define FT 9216               // one tile
#define FST (4 * FT)          // stage: Kh,Kl,Vh,Vl = 36864
#define FQ (2 * FST)          // Q region at 73728
#define FL_SMEM (FQ + 2 * FT) // 92160

__global__ void __launch_bounds__(128, 2) flash_bf(const ushort_t* __restrict__ QH,
                                                   const ushort_t* __restrict__ QL,
                                                   const ushort_t* __restrict__ KH,
                                                   const ushort_t* __restrict__ KL,
                                                   const ushort_t* __restrict__ VH,
                                                   const ushort_t* __restrict__ VL,
                                                   ushort_t* __restrict__ OH,
                                                   ushort_t* __restrict__ OL, int S) {
    extern __shared__ char smc[];
    uint32_t sb = stou(smc);

    int tid = threadIdx.x;
    int lane = tid & 31;
    int w = tid >> 5;
    int g = lane >> 2, t = lane & 3;

    int qb = blockIdx.x * 64;
    int bh = blockIdx.y;
    size_t hoff = (size_t)bh * S * HEAD_DIM;
    const ushort_t* qhp = QH + hoff;
    const ushort_t* qlp = QL + hoff;
    const ushort_t* khp = KH + hoff;
    const ushort_t* klp = KL + hoff;
    const ushort_t* vhp = VH + hoff;
    const ushort_t* vlp = VL + hoff;

    int nkb = qb / 64 + 1;

    // tile loader: 64 rows x 8 16B-segs = 512 cp.async / 128 thr = 4 each
    int rr = tid >> 1, sg2 = (tid & 1) * 4;   // rows 0..63, segs {0..3 | 4..7}
#define LOAD_TILE(dst, src)                                                   \
    do {                                                                      \
        uint32_t d_ = (dst) + (uint32_t)(rr * FPB + sg2 * 16);                \
        const ushort_t* s_ = (src) + rr * 64 + sg2 * 8;                       \
        cpasync16(d_, s_);           cpasync16(d_ + 16, s_ + 8);              \
        cpasync16(d_ + 32, s_ + 16); cpasync16(d_ + 48, s_ + 24);             \
    } while (0)

#define STAGE_KV(kb, st)                                                      \
    do {                                                                      \
        uint32_t s0_ = sb + (uint32_t)(st) * FST;                             \
        const ushort_t* o_ = (const ushort_t*)0 + (size_t)(kb) * 64 * HEAD_DIM;\
        size_t off_ = (size_t)(kb) * 64 * HEAD_DIM; (void)o_;                 \
        LOAD_TILE(s0_,          khp + off_);                                  \
        LOAD_TILE(s0_ + FT,     klp + off_);                                  \
        LOAD_TILE(s0_ + 2 * FT, vhp + off_);                                  \
        LOAD_TILE(s0_ + 3 * FT, vlp + off_);                                  \
        CP_COMMIT();                                                          \
    } while (0)

    STAGE_KV(0, 0);
    LOAD_TILE(sb + FQ, qhp + (size_t)qb * HEAD_DIM);
    LOAD_TILE(sb + FQ + FT, qlp + (size_t)qb * HEAD_DIM);
    CP_COMMIT();
    CP_WAIT0();
    __syncthreads();

    // hoist Q fragments (rows w*16..w*16+15, all 64 d)
    uint32_t qf_h[4][4], qf_l[4][4];
    {
        uint32_t a0 = sb + FQ + (uint32_t)((w * 16 + (lane & 15)) * FPB + (lane >> 4) * 16);
#pragma unroll
        for (int ks = 0; ks < 4; ++ks) {
            ldx4(qf_h[ks], a0 + ks * 32);
            ldx4(qf_l[ks], a0 + ks * 32 + FT);
        }
    }

    float cO[8][4];
#pragma unroll
    for (int nt = 0; nt < 8; ++nt)
#pragma unroll
        for (int q = 0; q < 4; ++q) cO[nt][q] = 0.0f;
    float m0 = -1e30f, m1 = -1e30f, l0 = 0.0f, l1 = 0.0f;

    for (int kb = 0; kb < nkb; ++kb) {
        int st = kb & 1;
        CP_WAIT0();
        __syncthreads();
        if (kb + 1 < nkb) STAGE_KV(kb + 1, st ^ 1);

        // ---- S = Q K^T ----
        float cS[8][4];
#pragma unroll
        for (int nt = 0; nt < 8; ++nt)
#pragma unroll
            for (int q = 0; q < 4; ++q) cS[nt][q] = 0.0f;

        uint32_t kBase = sb + (uint32_t)st * FST +
                         (uint32_t)((lane & 15) * FPB + (lane >> 4) * 16);
#pragma unroll
        for (int ks = 0; ks < 4; ++ks) {
#pragma unroll
            for (int np = 0; np < 4; ++np) {
                uint32_t a = kBase + (uint32_t)(np * 16 * FPB + ks * 32);
                uint32_t bh4[4], bl4[4];
                ldx4(bh4, a);
                ldx4(bl4, a + FT);
                mma_bf(cS[2 * np], qf_h[ks], bh4[0], bh4[2]);
                mma_bf(cS[2 * np], qf_l[ks], bh4[0], bh4[2]);
                mma_bf(cS[2 * np], qf_h[ks], bl4[0], bl4[2]);
                mma_bf(cS[2 * np + 1], qf_h[ks], bh4[1], bh4[3]);
                mma_bf(cS[2 * np + 1], qf_l[ks], bh4[1], bh4[3]);
                mma_bf(cS[2 * np + 1], qf_h[ks], bl4[1], bl4[3]);
            }
        }

        // ---- causal mask (diagonal block only) ----
        if (kb == nkb - 1) {
            int rg0 = qb + w * 16 + g, rg1 = rg0 + 8;
#pragma unroll
            for (int nt = 0; nt < 8; ++nt) {
                int c0 = kb * 64 + nt * 8 + 2 * t;
                if (c0 > rg0) cS[nt][0] = -1e30f;
                if (c0 + 1 > rg0) cS[nt][1] = -1e30f;
                if (c0 > rg1) cS[nt][2] = -1e30f;
                if (c0 + 1 > rg1) cS[nt][3] = -1e30f;
            }
        }

        // ---- online softmax; P packed to bf16 A-fragments in registers ----
        float mx0 = -1e30f, mx1 = -1e30f;
#pragma unroll
        for (int nt = 0; nt < 8; ++nt) {
            mx0 = fmaxf(mx0, fmaxf(cS[nt][0], cS[nt][1]));
            mx1 = fmaxf(mx1, fmaxf(cS[nt][2], cS[nt][3]));
        }
        mx0 = fmaxf(mx0, __shfl_xor_sync(0xffffffffu, mx0, 1));
        mx0 = fmaxf(mx0, __shfl_xor_sync(0xffffffffu, mx0, 2));
        mx1 = fmaxf(mx1, __shfl_xor_sync(0xffffffffu, mx1, 1));
        mx1 = fmaxf(mx1, __shfl_xor_sync(0xffffffffu, mx1, 2));

        float mn0 = fmaxf(m0, mx0), mn1 = fmaxf(m1, mx1);
        float a0 = __expf(m0 - mn0), a1 = __expf(m1 - mn1);
        m0 = mn0; m1 = mn1;

        uint32_t ph[4][4], pl[4][4];
        float s0 = 0.0f, s1 = 0.0f;
#pragma unroll
        for (int nt = 0; nt < 8; ++nt) {
            float p0 = __expf(cS[nt][0] - mn0);
            float p1 = __expf(cS[nt][1] - mn0);
            float p2 = __expf(cS[nt][2] - mn1);
            float p3 = __expf(cS[nt][3] - mn1);
            s0 += p0 + p1;
            s1 += p2 + p3;
            float h0 = bfr(p0), h1 = bfr(p1), h2 = bfr(p2), h3 = bfr(p3);
            int ks = nt >> 1;
            int o = (nt & 1) * 2;
            ph[ks][o] = bfpack(h0, h1);
            ph[ks][o + 1] = bfpack(h2, h3);
            pl[ks][o] = bfpack(p0 - h0, p1 - h1);
            pl[ks][o + 1] = bfpack(p2 - h2, p3 - h3);
        }
        s0 += __shfl_xor_sync(0xffffffffu, s0, 1);
        s0 += __shfl_xor_sync(0xffffffffu, s0, 2);
        s1 += __shfl_xor_sync(0xffffffffu, s1, 1);
        s1 += __shfl_xor_sync(0xffffffffu, s1, 2);
        l0 = l0 * a0 + s0;
        l1 = l1 * a1 + s1;

        // ---- O = O*alpha + P V ----
#pragma unroll
        for (int nt = 0; nt < 8; ++nt) {
            cO[nt][0] *= a0; cO[nt][1] *= a0;
            cO[nt][2] *= a1; cO[nt][3] *= a1;
        }
        uint32_t vBase = sb + (uint32_t)st * FST + 2 * FT +
                         (uint32_t)((lane & 15) * FPB + (lane >> 4) * 16);
#pragma unroll
        for (int ks = 0; ks < 4; ++ks) {
#pragma unroll
            for (int np = 0; np < 4; ++np) {
                uint32_t a = vBase + (uint32_t)(ks * 16 * FPB + np * 32);
                uint32_t vh4[4], vl4[4];
                ldx4t(vh4, a);
                ldx4t(vl4, a + FT);
                mma_bf(cO[2 * np], ph[ks], vh4[0], vh4[1]);
                mma_bf(cO[2 * np], pl[ks], vh4[0], vh4[1]);
                mma_bf(cO[2 * np], ph[ks], vl4[0], vl4[1]);
                mma_bf(cO[2 * np + 1], ph[ks], vh4[2], vh4[3]);
                mma_bf(cO[2 * np + 1], pl[ks], vh4[2], vh4[3]);
                mma_bf(cO[2 * np + 1], ph[ks], vl4[2], vl4[3]);
            }
        }
    }
#undef STAGE_KV
#undef LOAD_TILE

    // ---- finalize: scale by 1/l, split to bf16 hi/lo for the Wo GEMM ----
    float li0 = 1.0f / l0, li1 = 1.0f / l1;
    int b = bh >> 4, h = bh & 15;
    int row0 = qb + w * 16 + g;
    size_t base0 = ((size_t)(b * S + row0)) * D_MODEL + h * HEAD_DIM;
    size_t base1 = base0 + (size_t)8 * D_MODEL;
#pragma unroll
    for (int nt = 0; nt < 8; ++nt) {
        int d = nt * 8 + 2 * t;
        float o00 = cO[nt][0] * li0, o01 = cO[nt][1] * li0;
        float o10 = cO[nt][2] * li1, o11 = cO[nt][3] * li1;
        float h00 = bfr(o00), h01 = bfr(o01), h10 = bfr(o10), h11 = bfr(o11);
        *(uint32_t*)(OH + base0 + d) = bfpack(h00, h01);
        *(uint32_t*)(OL + base0 + d) = bfpack(o00 - h00, o01 - h01);
        *(uint32_t*)(OH + base1 + d) = bfpack(h10, h11);
        *(uint32_t*)(OL + base1 + d) = bfpack(o10 - h10, o11 - h11);
    }
}

// ---------------- host side ----------------
extern "C" void kernel_launch(void* const* d_in, const int* in_sizes, int n_in,
                              void* d_out, int out_size) {
    const float* x  = (const float*)d_in[0];
    const float* Wq = (const float*)d_in[1];
    const float* Wk = (const float*)d_in[2];
    const float* Wv = (const float*)d_in[3];
    const float* Wo = (const float*)d_in[4];

    int B = in_sizes[0] / (SEQ * D_MODEL);
    if (B < 1) B = 1;
    if (B > MAXB) B = MAXB;
    int T = B * SEQ;
    int BH = B * N_HEADS;

    float *q, *k;
    ushort_t *qh, *ql, *kh, *kl, *vh, *vl, *xh, *xl, *wh, *wl;
    cudaGetSymbolAddress((void**)&q, g_q);
    cudaGetSymbolAddress((void**)&k, g_k);
    cudaGetSymbolAddress((void**)&qh, g_qh);
    cudaGetSymbolAddress((void**)&ql, g_ql);
    cudaGetSymbolAddress((void**)&kh, g_kh);
    cudaGetSymbolAddress((void**)&kl, g_kl);
    cudaGetSymbolAddress((void**)&vh, g_vh);
    cudaGetSymbolAddress((void**)&vl, g_vl);
    cudaGetSymbolAddress((void**)&xh, g_xh);
    cudaGetSymbolAddress((void**)&xl, g_xl);
    cudaGetSymbolAddress((void**)&wh, g_wh);
    cudaGetSymbolAddress((void**)&wl, g_wl);

    const int GSMEM = 2 * STAGEB;   // 81920
    cudaFuncSetAttribute(tc_gemm<1>, cudaFuncAttributeMaxDynamicSharedMemorySize, GSMEM);
    cudaFuncSetAttribute(tc_gemm<0>, cudaFuncAttributeMaxDynamicSharedMemorySize, GSMEM);
    cudaFuncSetAttribute(flash_bf, cudaFuncAttributeMaxDynamicSharedMemorySize, FL_SMEM);

    const size_t WSZ = (size_t)D_MODEL * D_MODEL;

    // 1) split x and weights into bf16 hi/lo
    int n4 = T * D_MODEL / 4;
    split_kernel<<<(n4 + 255) / 256, 256>>>((const float4*)x, (uint2*)xh, (uint2*)xl, n4);
    splitw_kernel<<<dim3(256, 4), 256>>>(Wq, Wk, Wv, Wo, wh, wl);

    // 2) QKV projections: q,k fp32; V written pre-split bf16
    tc_gemm<1><<<dim3(T / 128, D_MODEL / 128, 3), 256, GSMEM>>>(
        xh, xl, wh, wl, q, k, vh, vl, SEQ);

    // 3) fused RoPE + split for Q (scaled) and K
    int tot = BH * SEQ * 32;
    rope_split<<<(tot + 255) / 256, 256>>>(q, k, qh, ql, kh, kl, BH, SEQ);

    // 4) flash attention (all-bf16 pipeline; writes split hi/lo O)
    flash_bf<<<dim3(SEQ / 64, BH), 128, FL_SMEM>>>(qh, ql, kh, kl, vh, vl, xh, xl, SEQ);

    // 5) output projection
    tc_gemm<0><<<dim3(T / 128, D_MODEL / 128, 1), 256, GSMEM>>>(
        xh, xl, wh + 3 * WSZ, wl + 3 * WSZ, (float*)d_out, nullptr,
        nullptr, nullptr, SEQ);
}

// round 13
// speedup vs baseline: 1.5658x; 1.5658x over previous
#include <cuda_runtime.h>
#include <cuda_fp16.h>
#include <math.h>
#include <stdint.h>

#define D_MODEL 1024
#define N_HEADS 16
#define HEAD_DIM 64
#define SEQ 2048
#define MAXB 2

typedef unsigned short ushort_t;

// ---------------- scratch (no allocations allowed) ----------------
__device__ __align__(1024) float g_q[MAXB * N_HEADS * SEQ * HEAD_DIM];
__device__ __align__(1024) float g_k[MAXB * N_HEADS * SEQ * HEAD_DIM];
__device__ __align__(1024) ushort_t g_qh[MAXB * N_HEADS * SEQ * HEAD_DIM];  // fp16 hi Q
__device__ __align__(1024) ushort_t g_ql[MAXB * N_HEADS * SEQ * HEAD_DIM];  // fp16 lo Q
__device__ __align__(1024) ushort_t g_kh[MAXB * N_HEADS * SEQ * HEAD_DIM];  // fp16 K
__device__ __align__(1024) ushort_t g_vh[MAXB * N_HEADS * SEQ * HEAD_DIM];  // fp16 V
__device__ __align__(1024) ushort_t g_xh[MAXB * SEQ * D_MODEL];   // fp16 hi of x / attn-out
__device__ __align__(1024) ushort_t g_xl[MAXB * SEQ * D_MODEL];   // fp16 lo
__device__ __align__(1024) ushort_t g_wh[4 * D_MODEL * D_MODEL];  // fp16 weights (rounded)

// ---------------- helpers ----------------
__device__ __forceinline__ uint32_t stou(const void* p) {
    uint32_t a;
    asm("{ .reg .u64 t; cvta.to.shared.u64 t, %1; cvt.u32.u64 %0, t; }"
        : "=r"(a) : "l"(p));
    return a;
}
__device__ __forceinline__ uint32_t hpack(float lo, float hi) {
    uint32_t r;
    asm("cvt.rn.f16x2.f32 %0, %1, %2;" : "=r"(r) : "f"(hi), "f"(lo));
    return r;
}
__device__ __forceinline__ float hr(float x) {   // round to fp16, back to float
    return __half2float(__float2half_rn(x));
}
__device__ __forceinline__ ushort_t hu(float x) {
    __half_raw r = __float2half_rn(x);
    return r.x;
}
__device__ __forceinline__ void cpasync16(uint32_t dst, const void* src) {
    asm volatile("cp.async.cg.shared.global [%0], [%1], 16;"
                 :: "r"(dst), "l"(src) : "memory");
}
#define CP_COMMIT() asm volatile("cp.async.commit_group;" ::: "memory")
#define CP_WAIT1()  asm volatile("cp.async.wait_group 1;" ::: "memory")
#define CP_WAIT0()  asm volatile("cp.async.wait_group 0;" ::: "memory")

__device__ __forceinline__ void ldx4(uint32_t r[4], uint32_t addr) {
    asm volatile("ldmatrix.sync.aligned.m8n8.x4.shared.b16 {%0,%1,%2,%3}, [%4];"
                 : "=r"(r[0]), "=r"(r[1]), "=r"(r[2]), "=r"(r[3]) : "r"(addr));
}
__device__ __forceinline__ void ldx4t(uint32_t r[4], uint32_t addr) {
    asm volatile("ldmatrix.sync.aligned.m8n8.x4.trans.shared.b16 {%0,%1,%2,%3}, [%4];"
                 : "=r"(r[0]), "=r"(r[1]), "=r"(r[2]), "=r"(r[3]) : "r"(addr));
}
__device__ __forceinline__ void mma_f16(float c[4], const uint32_t a[4],
                                        uint32_t b0, uint32_t b1) {
    asm volatile(
        "mma.sync.aligned.m16n8k16.row.col.f32.f16.f16.f32 "
        "{%0,%1,%2,%3}, {%4,%5,%6,%7}, {%8,%9}, {%0,%1,%2,%3};"
        : "+f"(c[0]), "+f"(c[1]), "+f"(c[2]), "+f"(c[3])
        : "r"(a[0]), "r"(a[1]), "r"(a[2]), "r"(a[3]), "r"(b0), "r"(b1));
}

// ---------------- split kernels ----------------
// x -> fp16 hi + fp16 lo (A operand of projections)
__global__ void split_kernel(const float4* __restrict__ src, uint2* __restrict__ hi,
                             uint2* __restrict__ lo, int n4) {
    int i = blockIdx.x * 256 + threadIdx.x;
    if (i >= n4) return;
    float4 v = src[i];
    float hx = hr(v.x), hy = hr(v.y), hz = hr(v.z), hw = hr(v.w);
    uint2 h, l;
    h.x = hpack(hx, hy); h.y = hpack(hz, hw);
    l.x = hpack(v.x - hx, v.y - hy); l.y = hpack(v.z - hz, v.w - hw);
    hi[i] = h; lo[i] = l;
}

// weights -> fp16 (B operand; rounding only, no lo needed for 2-pass)
__global__ void splitw_kernel(const float* __restrict__ w0, const float* __restrict__ w1,
                              const float* __restrict__ w2, const float* __restrict__ w3,
                              ushort_t* __restrict__ hi) {
    int y = blockIdx.y;
    const float* w = (y == 0) ? w0 : (y == 1) ? w1 : (y == 2) ? w2 : w3;
    const int n4 = (D_MODEL * D_MODEL) / 4;
    const float4* s4 = (const float4*)w;
    uint2* h4 = (uint2*)(hi + (size_t)y * D_MODEL * D_MODEL);
    for (int i = blockIdx.x * 256 + threadIdx.x; i < n4; i += gridDim.x * 256) {
        float4 v = s4[i];
        uint2 h;
        h.x = hpack(hr(v.x), hr(v.y));
        h.y = hpack(hr(v.z), hr(v.w));
        h4[i] = h;
    }
}

// ---------------------------------------------------------------------------
// fp16 2-pass GEMM: D = (Ah+Al)*Bh^T via m16n8k16 + ldmatrix.
// Tile 128x128, BK=32, 8 warps (2x4), warp tile 64x32, cp.async 2-stage.
// QKV=1: z=0 -> q fp32 [B,H,S,HD]; z=1 -> k fp32; z=2 -> V fp16 VH.
// QKV=0: fp32 row-major out.
// ---------------------------------------------------------------------------
#define GP 80                 // bytes per 32-half row (64 + 16 pad)
#define OPB (128 * GP)        // 10240
#define STAGEB (3 * OPB)      // Ah, Al, Bh = 30720
#define NCH (D_MODEL / 32)    // 32

template <int QKV>
__global__ void __launch_bounds__(256, 1) tc_gemm(
    const ushort_t* __restrict__ Ah, const ushort_t* __restrict__ Al,
    const ushort_t* __restrict__ Wh,
    float* __restrict__ C0, float* __restrict__ C1,
    ushort_t* __restrict__ VH, int S) {
    extern __shared__ char smc[];
    uint32_t sb = stou(smc);

    int tid = threadIdx.x;
    int lane = tid & 31;
    int wid = tid >> 5;
    int warp_m = wid >> 2;
    int warp_n = wid & 3;

    int mBase = blockIdx.x * 128;
    int nBase = blockIdx.y * 128;

    const ushort_t* Bh = Wh;
    if (QKV) Bh = Wh + (size_t)blockIdx.z * D_MODEL * D_MODEL;

    int r = tid >> 2, sg = tid & 3;
    const ushort_t* pAh = Ah + (size_t)(mBase + r) * D_MODEL + sg * 8;
    const ushort_t* pAl = Al + (size_t)(mBase + r) * D_MODEL + sg * 8;
    const ushort_t* pBh = Bh + (size_t)(nBase + r) * D_MODEL + sg * 8;
    uint32_t dst0 = (uint32_t)(r * GP + sg * 16);
    const uint32_t rStep = 64 * GP;
    const size_t gStep = (size_t)64 * D_MODEL;

#define STAGE(buf, k0)                                                        \
    do {                                                                      \
        uint32_t s0 = sb + (uint32_t)(buf) * STAGEB + dst0;                   \
        cpasync16(s0,                   pAh + (k0));                          \
        cpasync16(s0 + rStep,           pAh + (k0) + gStep);                  \
        cpasync16(s0 + OPB,             pAl + (k0));                          \
        cpasync16(s0 + OPB + rStep,     pAl + (k0) + gStep);                  \
        cpasync16(s0 + 2 * OPB,         pBh + (k0));                          \
        cpasync16(s0 + 2 * OPB + rStep, pBh + (k0) + gStep);                  \
    } while (0)

    float c[4][4][4];
#pragma unroll
    for (int mi = 0; mi < 4; ++mi)
#pragma unroll
        for (int ni = 0; ni < 4; ++ni)
#pragma unroll
            for (int q = 0; q < 4; ++q) c[mi][ni][q] = 0.0f;

    uint32_t aOff = (uint32_t)((warp_m * 64 + (lane & 15)) * GP + (lane >> 4) * 16);
    uint32_t bOff = (uint32_t)((warp_n * 32 + (lane & 15)) * GP + (lane >> 4) * 16);

    STAGE(0, 0);
    CP_COMMIT();

    for (int ch = 0; ch < NCH; ++ch) {
        if (ch + 1 < NCH) {
            STAGE((ch + 1) & 1, (ch + 1) * 32);
            CP_COMMIT();
            CP_WAIT1();
        } else {
            CP_WAIT0();
        }
        __syncthreads();

        uint32_t stg = sb + (uint32_t)(ch & 1) * STAGEB;
#pragma unroll
        for (int ks = 0; ks < 2; ++ks) {
            uint32_t ah[4][4], al[4][4], bh4[2][4];
#pragma unroll
            for (int mi = 0; mi < 4; ++mi) {
                uint32_t a = stg + aOff + (uint32_t)(mi * 16 * GP + ks * 32);
                ldx4(ah[mi], a);
                ldx4(al[mi], a + OPB);
            }
#pragma unroll
            for (int np = 0; np < 2; ++np) {
                uint32_t a = stg + 2 * OPB + bOff + (uint32_t)(np * 16 * GP + ks * 32);
                ldx4(bh4[np], a);
            }
#pragma unroll
            for (int mi = 0; mi < 4; ++mi)
#pragma unroll
                for (int np = 0; np < 2; ++np) {
                    mma_f16(c[mi][2 * np], ah[mi], bh4[np][0], bh4[np][2]);
                    mma_f16(c[mi][2 * np], al[mi], bh4[np][0], bh4[np][2]);
                    mma_f16(c[mi][2 * np + 1], ah[mi], bh4[np][1], bh4[np][3]);
                    mma_f16(c[mi][2 * np + 1], al[mi], bh4[np][1], bh4[np][3]);
                }
        }
        __syncthreads();
    }
#undef STAGE

    int g = lane >> 2, t = lane & 3;
#pragma unroll
    for (int mi = 0; mi < 4; ++mi) {
#pragma unroll
        for (int ni = 0; ni < 4; ++ni) {
            int r0 = mBase + warp_m * 64 + mi * 16 + g;
            int cc = nBase + warp_n * 32 + ni * 8 + 2 * t;
            float2 v0 = make_float2(c[mi][ni][0], c[mi][ni][1]);
            float2 v1 = make_float2(c[mi][ni][2], c[mi][ni][3]);
            if (!QKV) {
                *(float2*)(C0 + (size_t)r0 * D_MODEL + cc) = v0;
                *(float2*)(C0 + (size_t)(r0 + 8) * D_MODEL + cc) = v1;
            } else {
                int h = cc >> 6, hd = cc & 63;
                int b0 = r0 / S, s0 = r0 - b0 * S;
                int r1 = r0 + 8;
                int b1 = r1 / S, s1 = r1 - b1 * S;
                size_t o0 = (((size_t)b0 * N_HEADS + h) * S + s0) * HEAD_DIM + hd;
                size_t o1 = (((size_t)b1 * N_HEADS + h) * S + s1) * HEAD_DIM + hd;
                if (blockIdx.z == 2) {
                    *(uint32_t*)(VH + o0) = hpack(hr(v0.x), hr(v0.y));
                    *(uint32_t*)(VH + o1) = hpack(hr(v1.x), hr(v1.y));
                } else {
                    float* C = (blockIdx.z == 0) ? C0 : C1;
                    *(float2*)(C + o0) = v0;
                    *(float2*)(C + o1) = v1;
                }
            }
        }
    }
}

// ---------------------------------------------------------------------------
// Fused RoPE + fp16 split(Q, pre-scaled 1/8) / round(K). [BH, S, HD].
// ---------------------------------------------------------------------------
__global__ void rope_split(const float* __restrict__ q, const float* __restrict__ k,
                           ushort_t* __restrict__ qh, ushort_t* __restrict__ ql,
                           ushort_t* __restrict__ kh, int BH, int S) {
    int idx = blockIdx.x * blockDim.x + threadIdx.x;
    int total = BH * S * 32;
    if (idx >= total) return;
    int j = idx & 31;
    int s = (idx >> 5) % S;
    int bh = idx / (32 * S);

    float inv = powf(10000.0f, -(float)j / 32.0f);
    float ang = (float)s * inv;
    float sn, cs;
    sincosf(ang, &sn, &cs);

    size_t base = ((size_t)bh * S + s) * HEAD_DIM;
    float q1 = q[base + j], q2 = q[base + j + 32];
    float qa = (q1 * cs - q2 * sn) * 0.125f;
    float qb = (q2 * cs + q1 * sn) * 0.125f;
    float qah = hr(qa), qbh = hr(qb);
    qh[base + j] = hu(qa);           ql[base + j] = hu(qa - qah);
    qh[base + j + 32] = hu(qb);      ql[base + j + 32] = hu(qb - qbh);

    float k1 = k[base + j], k2 = k[base + j + 32];
    kh[base + j] = hu(k1 * cs - k2 * sn);
    kh[base + j + 32] = hu(k2 * cs + k1 * sn);
}

// ---------------------------------------------------------------------------
// Flash attention, fp16 2-pass. 64 q/CTA, 64-key tiles, 4 warps; warp owns
// rows [16w,16w+16) end-to-end. K/V are single fp16 tiles (2-stage cp.async);
// Q split hi/lo hoisted into registers; P split hi/lo in registers.
// ---------------------------------------------------------------------------
#define FPB 144               // bytes per 64-half row (128 + 16 pad)
#define FT 9216               // one tile
#define FST (2 * FT)          // stage: Kh, Vh = 18432
#define FQ (2 * FST)          // Q region at 36864
#define FL_SMEM (FQ + 2 * FT) // 55296

__global__ void __launch_bounds__(128, 2) flash_f16(const ushort_t* __restrict__ QH,
                                                    const ushort_t* __restrict__ QL,
                                                    const ushort_t* __restrict__ KH,
                                                    const ushort_t* __restrict__ VH,
                                                    ushort_t* __restrict__ OH,
                                                    ushort_t* __restrict__ OL, int S) {
    extern __shared__ char smc[];
    uint32_t sb = stou(smc);

    int tid = threadIdx.x;
    int lane = tid & 31;
    int w = tid >> 5;
    int g = lane >> 2, t = lane & 3;

    int qb = blockIdx.x * 64;
    int bh = blockIdx.y;
    size_t hoff = (size_t)bh * S * HEAD_DIM;
    const ushort_t* qhp = QH + hoff;
    const ushort_t* qlp = QL + hoff;
    const ushort_t* khp = KH + hoff;
    const ushort_t* vhp = VH + hoff;

    int nkb = qb / 64 + 1;

    int rr = tid >> 1, sg2 = (tid & 1) * 4;
#define LOAD_TILE(dst, src)                                                   \
    do {                                                                      \
        uint32_t d_ = (dst) + (uint32_t)(rr * FPB + sg2 * 16);                \
        const ushort_t* s_ = (src) + rr * 64 + sg2 * 8;                       \
        cpasync16(d_, s_);           cpasync16(d_ + 16, s_ + 8);              \
        cpasync16(d_ + 32, s_ + 16); cpasync16(d_ + 48, s_ + 24);             \
    } while (0)

#define STAGE_KV(kb, st)                                                      \
    do {                                                                      \
        uint32_t s0_ = sb + (uint32_t)(st) * FST;                             \
        size_t off_ = (size_t)(kb) * 64 * HEAD_DIM;                           \
        LOAD_TILE(s0_,      khp + off_);                                      \
        LOAD_TILE(s0_ + FT, vhp + off_);                                      \
        CP_COMMIT();                                                          \
    } while (0)

    STAGE_KV(0, 0);
    LOAD_TILE(sb + FQ, qhp + (size_t)qb * HEAD_DIM);
    LOAD_TILE(sb + FQ + FT, qlp + (size_t)qb * HEAD_DIM);
    CP_COMMIT();
    CP_WAIT0();
    __syncthreads();

    // hoist Q fragments (rows w*16..w*16+15, all 64 d)
    uint32_t qf_h[4][4], qf_l[4][4];
    {
        uint32_t a0 = sb + FQ + (uint32_t)((w * 16 + (lane & 15)) * FPB + (lane >> 4) * 16);
#pragma unroll
        for (int ks = 0; ks < 4; ++ks) {
            ldx4(qf_h[ks], a0 + ks * 32);
            ldx4(qf_l[ks], a0 + ks * 32 + FT);
        }
    }

    float cO[8][4];
#pragma unroll
    for (int nt = 0; nt < 8; ++nt)
#pragma unroll
        for (int q = 0; q < 4; ++q) cO[nt][q] = 0.0f;
    float m0 = -1e30f, m1 = -1e30f, l0 = 0.0f, l1 = 0.0f;

    for (int kb = 0; kb < nkb; ++kb) {
        int st = kb & 1;
        CP_WAIT0();
        __syncthreads();
        if (kb + 1 < nkb) STAGE_KV(kb + 1, st ^ 1);

        // ---- S = Q K^T (2-pass: (Qh+Ql)·Kh) ----
        float cS[8][4];
#pragma unroll
        for (int nt = 0; nt < 8; ++nt)
#pragma unroll
            for (int q = 0; q < 4; ++q) cS[nt][q] = 0.0f;

        uint32_t kBase = sb + (uint32_t)st * FST +
                         (uint32_t)((lane & 15) * FPB + (lane >> 4) * 16);
#pragma unroll
        for (int ks = 0; ks < 4; ++ks) {
#pragma unroll
            for (int np = 0; np < 4; ++np) {
                uint32_t a = kBase + (uint32_t)(np * 16 * FPB + ks * 32);
                uint32_t bh4[4];
                ldx4(bh4, a);
                mma_f16(cS[2 * np], qf_h[ks], bh4[0], bh4[2]);
                mma_f16(cS[2 * np], qf_l[ks], bh4[0], bh4[2]);
                mma_f16(cS[2 * np + 1], qf_h[ks], bh4[1], bh4[3]);
                mma_f16(cS[2 * np + 1], qf_l[ks], bh4[1], bh4[3]);
            }
        }

        // ---- causal mask (diagonal block only) ----
        if (kb == nkb - 1) {
            int rg0 = qb + w * 16 + g, rg1 = rg0 + 8;
#pragma unroll
            for (int nt = 0; nt < 8; ++nt) {
                int c0 = kb * 64 + nt * 8 + 2 * t;
                if (c0 > rg0) cS[nt][0] = -1e30f;
                if (c0 + 1 > rg0) cS[nt][1] = -1e30f;
                if (c0 > rg1) cS[nt][2] = -1e30f;
                if (c0 + 1 > rg1) cS[nt][3] = -1e30f;
            }
        }

        // ---- online softmax; P split to fp16 hi/lo in registers ----
        float mx0 = -1e30f, mx1 = -1e30f;
#pragma unroll
        for (int nt = 0; nt < 8; ++nt) {
            mx0 = fmaxf(mx0, fmaxf(cS[nt][0], cS[nt][1]));
            mx1 = fmaxf(mx1, fmaxf(cS[nt][2], cS[nt][3]));
        }
        mx0 = fmaxf(mx0, __shfl_xor_sync(0xffffffffu, mx0, 1));
        mx0 = fmaxf(mx0, __shfl_xor_sync(0xffffffffu, mx0, 2));
        mx1 = fmaxf(mx1, __shfl_xor_sync(0xffffffffu, mx1, 1));
        mx1 = fmaxf(mx1, __shfl_xor_sync(0xffffffffu, mx1, 2));

        float mn0 = fmaxf(m0, mx0), mn1 = fmaxf(m1, mx1);
        float a0 = __expf(m0 - mn0), a1 = __expf(m1 - mn1);
        m0 = mn0; m1 = mn1;

        uint32_t ph[4][4], pl[4][4];
        float s0 = 0.0f, s1 = 0.0f;
#pragma unroll
        for (int nt = 0; nt < 8; ++nt) {
            float p0 = __expf(cS[nt][0] - mn0);
            float p1 = __expf(cS[nt][1] - mn0);
            float p2 = __expf(cS[nt][2] - mn1);
            float p3 = __expf(cS[nt][3] - mn1);
            s0 += p0 + p1;
            s1 += p2 + p3;
            float h0 = hr(p0), h1 = hr(p1), h2 = hr(p2), h3 = hr(p3);
            int ks = nt >> 1;
            int o = (nt & 1) * 2;
            ph[ks][o] = hpack(h0, h1);
            ph[ks][o + 1] = hpack(h2, h3);
            pl[ks][o] = hpack(p0 - h0, p1 - h1);
            pl[ks][o + 1] = hpack(p2 - h2, p3 - h3);
        }
        s0 += __shfl_xor_sync(0xffffffffu, s0, 1);
        s0 += __shfl_xor_sync(0xffffffffu, s0, 2);
        s1 += __shfl_xor_sync(0xffffffffu, s1, 1);
        s1 += __shfl_xor_sync(0xffffffffu, s1, 2);
        l0 = l0 * a0 + s0;
        l1 = l1 * a1 + s1;

        // ---- O = O*alpha + (Ph+Pl)·Vh ----
#pragma unroll
        for (int nt = 0; nt < 8; ++nt) {
            cO[nt][0] *= a0; cO[nt][1] *= a0;
            cO[nt][2] *= a1; cO[nt][3] *= a1;
        }
        uint32_t vBase = sb + (uint32_t)st * FST + FT +
                         (uint32_t)((lane & 15) * FPB + (lane >> 4) * 16);
#pragma unroll
        for (int ks = 0; ks < 4; ++ks) {
#pragma unroll
            for (int np = 0; np < 4; ++np) {
                uint32_t a = vBase + (uint32_t)(ks * 16 * FPB + np * 32);
                uint32_t vh4[4];
                ldx4t(vh4, a);
                mma_f16(cO[2 * np], ph[ks], vh4[0], vh4[1]);
                mma_f16(cO[2 * np], pl[ks], vh4[0], vh4[1]);
                mma_f16(cO[2 * np + 1], ph[ks], vh4[2], vh4[3]);
                mma_f16(cO[2 * np + 1], pl[ks], vh4[2], vh4[3]);
            }
        }
    }
#undef STAGE_KV
#undef LOAD_TILE

    // ---- finalize: scale by 1/l, split to fp16 hi/lo for the Wo GEMM ----
    float li0 = 1.0f / l0, li1 = 1.0f / l1;
    int b = bh >> 4, h = bh & 15;
    int row0 = qb + w * 16 + g;
    size_t base0 = ((size_t)(b * S + row0)) * D_MODEL + h * HEAD_DIM;
    size_t base1 = base0 + (size_t)8 * D_MODEL;
#pragma unroll
    for (int nt = 0; nt < 8; ++nt) {
        int d = nt * 8 + 2 * t;
        float o00 = cO[nt][0] * li0, o01 = cO[nt][1] * li0;
        float o10 = cO[nt][2] * li1, o11 = cO[nt][3] * li1;
        float h00 = hr(o00), h01 = hr(o01), h10 = hr(o10), h11 = hr(o11);
        *(uint32_t*)(OH + base0 + d) = hpack(h00, h01);
        *(uint32_t*)(OL + base0 + d) = hpack(o00 - h00, o01 - h01);
        *(uint32_t*)(OH + base1 + d) = hpack(h10, h11);
        *(uint32_t*)(OL + base1 + d) = hpack(o10 - h10, o11 - h11);
    }
}

// ---------------- host side ----------------
extern "C" void kernel_launch(void* const* d_in, const int* in_sizes, int n_in,
                              void* d_out, int out_size) {
    const float* x  = (const float*)d_in[0];
    const float* Wq = (const float*)d_in[1];
    const float* Wk = (const float*)d_in[2];
    const float* Wv = (const float*)d_in[3];
    const float* Wo = (const float*)d_in[4];

    int B = in_sizes[0] / (SEQ * D_MODEL);
    if (B < 1) B = 1;
    if (B > MAXB) B = MAXB;
    int T = B * SEQ;
    int BH = B * N_HEADS;

    float *q, *k;
    ushort_t *qh, *ql, *kh, *vh, *xh, *xl, *wh;
    cudaGetSymbolAddress((void**)&q, g_q);
    cudaGetSymbolAddress((void**)&k, g_k);
    cudaGetSymbolAddress((void**)&qh, g_qh);
    cudaGetSymbolAddress((void**)&ql, g_ql);
    cudaGetSymbolAddress((void**)&kh, g_kh);
    cudaGetSymbolAddress((void**)&vh, g_vh);
    cudaGetSymbolAddress((void**)&xh, g_xh);
    cudaGetSymbolAddress((void**)&xl, g_xl);
    cudaGetSymbolAddress((void**)&wh, g_wh);

    const int GSMEM = 2 * STAGEB;   // 61440
    cudaFuncSetAttribute(tc_gemm<1>, cudaFuncAttributeMaxDynamicSharedMemorySize, GSMEM);
    cudaFuncSetAttribute(tc_gemm<0>, cudaFuncAttributeMaxDynamicSharedMemorySize, GSMEM);
    cudaFuncSetAttribute(flash_f16, cudaFuncAttributeMaxDynamicSharedMemorySize, FL_SMEM);

    const size_t WSZ = (size_t)D_MODEL * D_MODEL;

    // 1) split x (fp16 hi/lo) and round weights (fp16)
    int n4 = T * D_MODEL / 4;
    split_kernel<<<(n4 + 255) / 256, 256>>>((const float4*)x, (uint2*)xh, (uint2*)xl, n4);
    splitw_kernel<<<dim3(256, 4), 256>>>(Wq, Wk, Wv, Wo, wh);

    // 2) QKV projections: q,k fp32; V written fp16
    tc_gemm<1><<<dim3(T / 128, D_MODEL / 128, 3), 256, GSMEM>>>(
        xh, xl, wh, q, k, vh, SEQ);

    // 3) fused RoPE: Q split fp16 hi/lo (scaled), K rounded fp16
    int tot = BH * SEQ * 32;
    rope_split<<<(tot + 255) / 256, 256>>>(q, k, qh, ql, kh, BH, SEQ);

    // 4) flash attention (fp16 2-pass; writes split hi/lo O)
    flash_f16<<<dim3(SEQ / 64, BH), 128, FL_SMEM>>>(qh, ql, kh, vh, xh, xl, SEQ);

    // 5) output projection
    tc_gemm<0><<<dim3(T / 128, D_MODEL / 128, 1), 256, GSMEM>>>(
        xh, xl, wh + 3 * WSZ, (float*)d_out, nullptr, nullptr, SEQ);
}